// round 11
// baseline (speedup 1.0000x reference)
#include <cuda_runtime.h>
#include <stdint.h>

// Problem constants (SHAPE = (16,1,1024,1024), RATIO = 0.25)
#define N_TOTAL   16777216
#define N_VEC     (N_TOTAL / 4)
#define K_SEL     4194304u
#define GRID_BIG  304
#define TPB       1024
#define FULL      0xFFFFFFFFu
#define NSEG      (GRID_BIG * 32)   // 9728 warp-private segments
#define SEG_CAP   1792              // >= N_TOTAL/NSEG = 1725 (absolute bound)
#define HBINS     8192              // sample histogram bins = bits[30:18]
#define H2BINS    4096              // refinement histogram: window bits [b:b-11]
#define S_BLOCKS  128               // 128*1024 = 131072 samples
#define R_HI      30848u            // sample-rank (from top) for T_hi (K_s - 12sigma)
#define R_LO      34688u            // sample-rank for T_lo (K_s + 12sigma)

// Device-global state (statically zero-initialized)
__device__ __align__(16) uint32_t g_hist[HBINS];
__device__ __align__(16) uint32_t g_h2[H2BINS];
__device__ uint32_t g_scratch2[NSEG * SEG_CAP];  // compacted window elements
__device__ uint32_t g_Tlo, g_Thi;
__device__ uint32_t g_cntAbove;                  // # elements >= T_hi
__device__ double   g_sum;                       // exact sum of elements >= T_hi
__device__ uint32_t g_doneS, g_doneM;            // completion counters

// ---------------------------------------------------------------------------
__device__ __forceinline__ float bce_loss(float x, float t) {
    // max(x,0) - x*t + log1p(exp(-|x|)); always >= 0 for t in [0,1)
    float e = __expf(-fabsf(x));
    float l = fmaxf(x, 0.0f) - x * t + __logf(1.0f + e);
    return fmaxf(l, 0.0f);   // keep sign bit 0 -> uint order == float order
}

// b = highest bit where window values can differ (clamped >= 11).
// All window v share bits [31:b+1] == pfx0; histogram indexes bits [b:b-11].
__device__ __forceinline__ void win_params(uint32_t Tlo, uint32_t Thi,
                                           uint32_t& pfx0, int& s3) {
    uint32_t m = Tlo ^ (Thi - 1u);
    int b = m ? (31 - __clz((int)m)) : 11;
    if (b < 11) b = 11;
    s3 = b - 11;                       // bin width = 2^s3 ulps
    pfx0 = Tlo >> (b + 1);
}

// ---------------------------------------------------------------------------
// ksample: zero g_h2; BCE on first 131072 elements -> 8192-bin coarse
// histogram; LAST block derives [T_lo,T_hi) and publishes it.
// ---------------------------------------------------------------------------
__global__ void __launch_bounds__(TPB) ksample(const float* __restrict__ pred,
                                               const float* __restrict__ tgt) {
    __shared__ uint32_t sh[HBINS];
    __shared__ uint32_t sscan[TPB];
    __shared__ uint32_t s_last;
    const int t = threadIdx.x;
    int gidx = blockIdx.x * TPB + t;
    if (gidx < H2BINS) g_h2[gidx] = 0u;            // 128K threads >= 4K bins
    for (int i = t; i < HBINS; i += TPB) sh[i] = 0u;
    __syncthreads();

    float l = bce_loss(pred[gidx], tgt[gidx]);     // one sample per thread
    atomicAdd(&sh[__float_as_uint(l) >> 18], 1u);
    __syncthreads();
    for (int i = t; i < HBINS; i += TPB) {
        uint32_t c = sh[i];
        if (c) atomicAdd(&g_hist[i], c);
    }
    __threadfence();
    if (t == 0)
        s_last = (atomicAdd(&g_doneS, 1u) == (uint32_t)(S_BLOCKS - 1)) ? 1u : 0u;
    __syncthreads();
    if (!s_last) return;

    // Last block: descending-rank scan of g_hist -> T_lo, T_hi.
    uint4 h0 = ((const uint4*)g_hist)[t * 2];
    uint4 h1 = ((const uint4*)g_hist)[t * 2 + 1];
    uint32_t hb[8] = {h0.x, h0.y, h0.z, h0.w, h1.x, h1.y, h1.z, h1.w};
    uint32_t part = 0;
#pragma unroll
    for (int j = 0; j < 8; j++) part += hb[j];
    sscan[t] = part;
    __syncthreads();
    for (int off = 1; off < TPB; off <<= 1) {       // inclusive suffix scan
        uint32_t v = (t + off < TPB) ? sscan[t + off] : 0u;
        __syncthreads();
        sscan[t] += v;
        __syncthreads();
    }
    uint32_t tail = sscan[t] - part;                // strictly-above count
    for (int j = 7; j >= 0; j--) {                  // bins high -> low
        uint32_t C = tail, h = hb[j];
        if (C < R_HI && C + h >= R_HI) g_Thi = ((uint32_t)(t * 8 + j) + 1u) << 18;
        if (C < R_LO && C + h >= R_LO) g_Tlo = ((uint32_t)(t * 8 + j)) << 18;
        tail += h;
    }
    // Reset state consumed this replay.
    for (int i = t; i < HBINS; i += TPB) g_hist[i] = 0u;
    if (t == 0) g_doneS = 0u;
}

// ---------------------------------------------------------------------------
// kmain: single full pass (hot loop identical to the 59.6us version):
//   exact sum/count of v>=T_hi; compact window elems into warp segments;
//   tail: each warp histograms its (L2-hot) segment into g_h2;
//   LAST block to finish: scan g_h2, compute mean, write out, re-zero state.
// ---------------------------------------------------------------------------
__global__ void __launch_bounds__(TPB) kmain(const float* __restrict__ pred,
                                             const float* __restrict__ tgt,
                                             float* __restrict__ out) {
    __shared__ float    wp[32];
    __shared__ uint32_t wc[32];
    __shared__ uint32_t s_last;
    const int t = threadIdx.x;
    const uint32_t Tlo = g_Tlo, Thi = g_Thi;       // scalars, L2-broadcast

    // --- Phase B: main streaming pass ---
    const uint32_t lane = t & 31u;
    const uint32_t lt   = (1u << lane) - 1u;
    const uint32_t seg  = blockIdx.x * 32u + (t >> 5);
    uint32_t wbase = seg * SEG_CAP;
    const uint32_t wstart = wbase;
    float fs = 0.0f;
    uint32_t ch = 0;

    int tid = blockIdx.x * TPB + t;
    const int stride = GRID_BIG * TPB;
    const float4* p4 = (const float4*)pred;
    const float4* t4 = (const float4*)tgt;

#define KM_PROC(PX, TX) do {                                          \
        uint32_t _v = __float_as_uint(bce_loss((PX), (TX)));          \
        bool _hi = _v >= Thi;                                         \
        if (_hi) { fs += __uint_as_float(_v); ch++; }                 \
        bool _w = (_v >= Tlo) && !_hi;                                \
        unsigned _mm = __ballot_sync(FULL, _w);                       \
        if (_w) g_scratch2[wbase + __popc(_mm & lt)] = _v;            \
        wbase += __popc(_mm);                                         \
    } while (0)

    for (int i = tid; i < N_VEC; i += 2 * stride) {   // warp-uniform guards
        float4 pa = p4[i], ta = t4[i];
        bool sec = (i + stride) < N_VEC;
        float4 pb, tb;
        if (sec) { pb = p4[i + stride]; tb = t4[i + stride]; }
        KM_PROC(pa.x, ta.x); KM_PROC(pa.y, ta.y);
        KM_PROC(pa.z, ta.z); KM_PROC(pa.w, ta.w);
        if (sec) {
            KM_PROC(pb.x, tb.x); KM_PROC(pb.y, tb.y);
            KM_PROC(pb.z, tb.z); KM_PROC(pb.w, tb.w);
        }
    }
#undef KM_PROC

    // Block-reduce exact sum/count of v >= T_hi.
#pragma unroll
    for (int o = 16; o; o >>= 1) {
        fs += __shfl_down_sync(FULL, fs, o);
        ch += __shfl_down_sync(FULL, ch, o);
    }
    if (lane == 0) { wp[t >> 5] = fs; wc[t >> 5] = ch; }
    __syncthreads();
    if (t == 0) {
        double d = 0.0; uint32_t c = 0;
#pragma unroll
        for (int i = 0; i < 32; i++) { d += (double)wp[i]; c += wc[i]; }
        atomicAdd(&g_sum, d);
        atomicAdd(&g_cntAbove, c);
    }

    // --- Phase C: histogram own segment (L2-hot) into g_h2 ---
    uint32_t pfx0; int s3; win_params(Tlo, Thi, pfx0, s3);
    __threadfence_block();                 // order own-warp stores before loads
    __syncwarp();
    const uint32_t nw = wbase - wstart;
    for (uint32_t j = lane; j < nw; j += 32) {
        uint32_t v = g_scratch2[wstart + j];
        atomicAdd(&g_h2[(v >> s3) & (H2BINS - 1)], 1u);
    }

    // --- Phase D: last-finishing block finalizes ---
    __threadfence();                       // publish h2/sum/cnt before counting
    __syncthreads();
    if (t == 0)
        s_last = (atomicAdd(&g_doneM, 1u) == (uint32_t)(GRID_BIG - 1)) ? 1u : 0u;
    __syncthreads();
    if (!s_last) return;

    __shared__ uint32_t sscan[TPB];
    __shared__ double   dp[32];
    __shared__ uint32_t s_B, s_need;
    const uint32_t kr = K_SEL - g_cntAbove;     // needed from the window

    uint4 h = ((const uint4*)g_h2)[t];          // coalesced: 4 bins/thread
    uint32_t hb[4] = {h.x, h.y, h.z, h.w};
    uint32_t part = hb[0] + hb[1] + hb[2] + hb[3];
    sscan[t] = part;
    __syncthreads();
    for (int off = 1; off < TPB; off <<= 1) {   // inclusive suffix scan
        uint32_t v = (t + off < TPB) ? sscan[t + off] : 0u;
        __syncthreads();
        sscan[t] += v;
        __syncthreads();
    }
    uint32_t tail = sscan[t] - part;            // count in chunks above t
    {
        uint32_t C = tail;
        for (int j = 3; j >= 0; j--) {          // bins high -> low
            uint32_t hh = hb[j];
            if (C < kr && C + hh >= kr) { s_B = (uint32_t)(t * 4 + j); s_need = kr - C; }
            C += hh;
        }
    }
    __syncthreads();
    const uint32_t B = s_B, need = s_need;

    // Contributions: full bins above B at midpoint, plus `need` elements at B.
    double ds = 0.0;
#pragma unroll
    for (int j = 0; j < 4; j++) {
        uint32_t idx = (uint32_t)(t * 4 + j);
        uint32_t hh = hb[j];
        if ((idx > B && hh) || idx == B) {
            uint32_t bits = (((pfx0 << 12) | idx) << s3) |
                            (s3 ? (1u << (s3 - 1)) : 0u);   // bin midpoint
            double m = (double)__uint_as_float(bits);
            ds += (idx > B) ? (double)hh * m : (double)need * m;
        }
    }
#pragma unroll
    for (int o = 16; o; o >>= 1) ds += __shfl_down_sync(FULL, ds, o);
    if (lane == 0) dp[t >> 5] = ds;
    __syncthreads();
    if (t == 0) {
        double tot = g_sum;
#pragma unroll
        for (int i = 0; i < 32; i++) tot += dp[i];
        out[0] = (float)(tot / (double)K_SEL);
    }
    __syncthreads();
    // Re-zero scalars for the next graph replay (g_h2 zeroed by ksample,
    // g_hist zeroed by ksample's last block).
    if (t == 0) { g_sum = 0.0; g_cntAbove = 0u; g_doneM = 0u; }
}

// ---------------------------------------------------------------------------
extern "C" void kernel_launch(void* const* d_in, const int* in_sizes, int n_in,
                              void* d_out, int out_size) {
    (void)in_sizes; (void)n_in; (void)out_size;
    const float* pred = (const float*)d_in[0];
    const float* tgt  = (const float*)d_in[1];
    float* out = (float*)d_out;

    ksample<<<S_BLOCKS, TPB>>>(pred, tgt);
    kmain<<<GRID_BIG, TPB>>>(pred, tgt, out);
}

// round 12
// speedup vs baseline: 1.0043x; 1.0043x over previous
#include <cuda_runtime.h>
#include <stdint.h>

// Problem constants (SHAPE = (16,1,1024,1024), RATIO = 0.25)
#define N_TOTAL   16777216
#define N_VEC     (N_TOTAL / 4)
#define K_SEL     4194304u
#define GRID_BIG  304
#define TPB       1024
#define FULL      0xFFFFFFFFu
#define HBINS     8192              // sample histogram bins = bits[30:18]
#define H2BINS    4096              // refinement histogram: window bits [b:b-11]
#define S_BLOCKS  128               // 128*1024 = 131072 samples
#define R_HI      30848u            // sample-rank (from top) for T_hi (K_s - 12sigma)
#define R_LO      34688u            // sample-rank for T_lo (K_s + 12sigma)

// Device-global state (statically zero-initialized)
__device__ __align__(16) uint32_t g_hist[HBINS];
__device__ __align__(16) uint32_t g_h2[H2BINS];
__device__ uint32_t g_Tlo, g_Thi;
__device__ uint32_t g_cntAbove;                  // # elements >= T_hi
__device__ double   g_sum;                       // exact sum of elements >= T_hi
__device__ uint32_t g_doneS, g_doneM;            // completion counters

// ---------------------------------------------------------------------------
__device__ __forceinline__ float bce_loss(float x, float t) {
    // max(x,0) - x*t + log1p(exp(-|x|)); always >= 0 for t in [0,1)
    float e = __expf(-fabsf(x));
    float base = fmaf(-x, t, fmaxf(x, 0.0f));
    float l = base + __logf(1.0f + e);
    return fmaxf(l, 0.0f);   // keep sign bit 0 -> uint order == float order
}

// b = highest bit where window values can differ (clamped >= 11).
// All window v share bits [31:b+1] == pfx0; histogram indexes bits [b:b-11].
__device__ __forceinline__ void win_params(uint32_t Tlo, uint32_t Thi,
                                           uint32_t& pfx0, int& s3) {
    uint32_t m = Tlo ^ (Thi - 1u);
    int b = m ? (31 - __clz((int)m)) : 11;
    if (b < 11) b = 11;
    s3 = b - 11;                       // bin width = 2^s3 ulps
    pfx0 = Tlo >> (b + 1);
}

// ---------------------------------------------------------------------------
// ksample: zero g_h2; BCE on first 131072 elements -> 8192-bin coarse
// histogram; LAST block derives [T_lo,T_hi), publishes it, resets g_hist.
// ---------------------------------------------------------------------------
__global__ void __launch_bounds__(TPB) ksample(const float* __restrict__ pred,
                                               const float* __restrict__ tgt) {
    __shared__ uint32_t sh[HBINS];
    __shared__ uint32_t sscan[TPB];
    __shared__ uint32_t s_last;
    const int t = threadIdx.x;
    int gidx = blockIdx.x * TPB + t;
    if (gidx < H2BINS) g_h2[gidx] = 0u;            // 128K threads >= 4K bins
    for (int i = t; i < HBINS; i += TPB) sh[i] = 0u;
    __syncthreads();

    float l = bce_loss(pred[gidx], tgt[gidx]);     // one sample per thread
    atomicAdd(&sh[__float_as_uint(l) >> 18], 1u);
    __syncthreads();
    for (int i = t; i < HBINS; i += TPB) {
        uint32_t c = sh[i];
        if (c) atomicAdd(&g_hist[i], c);
    }
    __threadfence();
    if (t == 0)
        s_last = (atomicAdd(&g_doneS, 1u) == (uint32_t)(S_BLOCKS - 1)) ? 1u : 0u;
    __syncthreads();
    if (!s_last) return;

    // Last block: descending-rank scan of g_hist -> T_lo, T_hi.
    uint4 h0 = ((const uint4*)g_hist)[t * 2];
    uint4 h1 = ((const uint4*)g_hist)[t * 2 + 1];
    uint32_t hb[8] = {h0.x, h0.y, h0.z, h0.w, h1.x, h1.y, h1.z, h1.w};
    uint32_t part = 0;
#pragma unroll
    for (int j = 0; j < 8; j++) part += hb[j];
    sscan[t] = part;
    __syncthreads();
    for (int off = 1; off < TPB; off <<= 1) {       // inclusive suffix scan
        uint32_t v = (t + off < TPB) ? sscan[t + off] : 0u;
        __syncthreads();
        sscan[t] += v;
        __syncthreads();
    }
    uint32_t tail = sscan[t] - part;                // strictly-above count
    for (int j = 7; j >= 0; j--) {                  // bins high -> low
        uint32_t C = tail, h = hb[j];
        if (C < R_HI && C + h >= R_HI) g_Thi = ((uint32_t)(t * 8 + j) + 1u) << 18;
        if (C < R_LO && C + h >= R_LO) g_Tlo = ((uint32_t)(t * 8 + j)) << 18;
        tail += h;
    }
    // Reset state consumed this replay.
    for (int i = t; i < HBINS; i += TPB) g_hist[i] = 0u;
    if (t == 0) g_doneS = 0u;
}

// ---------------------------------------------------------------------------
// kmain: single full pass, lean hot loop (R8 style):
//   v >= T_hi          -> register sum + count (block-reduced at end)
//   T_lo <= v < T_hi   -> predicated atomicAdd into 4096-bin g_h2 (~490K RED
//                          ops, spread addresses -> ~1us chip-wide)
// LAST block to finish: coalesced scan of g_h2, mean, write out, reset state.
// ---------------------------------------------------------------------------
__global__ void __launch_bounds__(TPB) kmain(const float* __restrict__ pred,
                                             const float* __restrict__ tgt,
                                             float* __restrict__ out) {
    __shared__ float    wp[32];
    __shared__ uint32_t wc[32];
    __shared__ uint32_t s_last;
    const int t = threadIdx.x;
    const uint32_t Tlo = g_Tlo, Thi = g_Thi;       // scalars, L2-broadcast
    uint32_t pfx0; int s3; win_params(Tlo, Thi, pfx0, s3);

    float fs = 0.0f;
    uint32_t ch = 0;
    int tid = blockIdx.x * TPB + t;
    const int stride = GRID_BIG * TPB;
    const float4* p4 = (const float4*)pred;
    const float4* t4 = (const float4*)tgt;

#define KM_PROC(PX, TX) do {                                               \
        uint32_t _v = __float_as_uint(bce_loss((PX), (TX)));               \
        if (_v >= Thi)      { fs += __uint_as_float(_v); ch++; }           \
        else if (_v >= Tlo) atomicAdd(&g_h2[(_v >> s3) & (H2BINS - 1)], 1u); \
    } while (0)

    for (int i = tid; i < N_VEC; i += 2 * stride) {   // 2x unroll for MLP
        float4 pa = p4[i], ta = t4[i];
        bool sec = (i + stride) < N_VEC;
        float4 pb, tb;
        if (sec) { pb = p4[i + stride]; tb = t4[i + stride]; }
        KM_PROC(pa.x, ta.x); KM_PROC(pa.y, ta.y);
        KM_PROC(pa.z, ta.z); KM_PROC(pa.w, ta.w);
        if (sec) {
            KM_PROC(pb.x, tb.x); KM_PROC(pb.y, tb.y);
            KM_PROC(pb.z, tb.z); KM_PROC(pb.w, tb.w);
        }
    }
#undef KM_PROC

    // Block-reduce exact sum/count of v >= T_hi.
    const uint32_t lane = t & 31u;
#pragma unroll
    for (int o = 16; o; o >>= 1) {
        fs += __shfl_down_sync(FULL, fs, o);
        ch += __shfl_down_sync(FULL, ch, o);
    }
    if (lane == 0) { wp[t >> 5] = fs; wc[t >> 5] = ch; }
    __syncthreads();
    if (t == 0) {
        double d = 0.0; uint32_t c = 0;
#pragma unroll
        for (int i = 0; i < 32; i++) { d += (double)wp[i]; c += wc[i]; }
        atomicAdd(&g_sum, d);
        atomicAdd(&g_cntAbove, c);
    }

    // --- Last-finishing block finalizes ---
    __threadfence();                       // publish h2/sum/cnt before counting
    __syncthreads();
    if (t == 0)
        s_last = (atomicAdd(&g_doneM, 1u) == (uint32_t)(GRID_BIG - 1)) ? 1u : 0u;
    __syncthreads();
    if (!s_last) return;

    __shared__ uint32_t sscan[TPB];
    __shared__ double   dp[32];
    __shared__ uint32_t s_B, s_need;
    const uint32_t kr = K_SEL - g_cntAbove;     // needed from the window

    uint4 h = ((const uint4*)g_h2)[t];          // coalesced: 4 bins/thread
    uint32_t hb[4] = {h.x, h.y, h.z, h.w};
    uint32_t part = hb[0] + hb[1] + hb[2] + hb[3];
    sscan[t] = part;
    __syncthreads();
    for (int off = 1; off < TPB; off <<= 1) {   // inclusive suffix scan
        uint32_t v = (t + off < TPB) ? sscan[t + off] : 0u;
        __syncthreads();
        sscan[t] += v;
        __syncthreads();
    }
    uint32_t tail = sscan[t] - part;            // count in chunks above t
    {
        uint32_t C = tail;
        for (int j = 3; j >= 0; j--) {          // bins high -> low
            uint32_t hh = hb[j];
            if (C < kr && C + hh >= kr) { s_B = (uint32_t)(t * 4 + j); s_need = kr - C; }
            C += hh;
        }
    }
    __syncthreads();
    const uint32_t B = s_B, need = s_need;

    // Contributions: full bins above B at midpoint, plus `need` elements at B.
    double ds = 0.0;
#pragma unroll
    for (int j = 0; j < 4; j++) {
        uint32_t idx = (uint32_t)(t * 4 + j);
        uint32_t hh = hb[j];
        if ((idx > B && hh) || idx == B) {
            uint32_t bits = (((pfx0 << 12) | idx) << s3) |
                            (s3 ? (1u << (s3 - 1)) : 0u);   // bin midpoint
            double m = (double)__uint_as_float(bits);
            ds += (idx > B) ? (double)hh * m : (double)need * m;
        }
    }
#pragma unroll
    for (int o = 16; o; o >>= 1) ds += __shfl_down_sync(FULL, ds, o);
    if (lane == 0) dp[t >> 5] = ds;
    __syncthreads();
    if (t == 0) {
        double tot = g_sum;
#pragma unroll
        for (int i = 0; i < 32; i++) tot += dp[i];
        out[0] = (float)(tot / (double)K_SEL);
    }
    __syncthreads();
    // Re-zero scalars for next replay (g_h2/g_hist re-zeroed by next ksample).
    if (t == 0) { g_sum = 0.0; g_cntAbove = 0u; g_doneM = 0u; }
}

// ---------------------------------------------------------------------------
extern "C" void kernel_launch(void* const* d_in, const int* in_sizes, int n_in,
                              void* d_out, int out_size) {
    (void)in_sizes; (void)n_in; (void)out_size;
    const float* pred = (const float*)d_in[0];
    const float* tgt  = (const float*)d_in[1];
    float* out = (float*)d_out;

    ksample<<<S_BLOCKS, TPB>>>(pred, tgt);
    kmain<<<GRID_BIG, TPB>>>(pred, tgt, out);
}